// round 7
// baseline (speedup 1.0000x reference)
#include <cuda_runtime.h>
#include <cstdint>

// ---------------- problem constants ----------------
#define NPC       8000          // 64000/8 render points
#define NPC_PAD   8192
#define NREF      10000         // 80000/8 ref points
#define NREF_PAD  10240
#define PCPAIRS   (NPC_PAD / 2)    // 4096
#define REFPAIRS  (NREF_PAD / 2)   // 5120
#define TIL       256           // points per tile (both dims)
#define TILP      (TIL / 2)     // 128 packed pairs per tile
#define GRID_PC   (NPC_PAD / TIL)   // 32
#define GRID_REF  (NREF_PAD / TIL)  // 40
#define NBLOCKS   (GRID_PC * GRID_REF)   // 1280
#define NT        128
#define PAD_S     1e30f

typedef unsigned long long ull;

// ---------------- device scratch (no cudaMalloc allowed) ----------------
// Swept-pair packs, 4 ull per pair (32B, 16B-aligned): {x0,x1},{y0,y1},{s0,s1},pad
__device__ __align__(16) ull g_pcPair[PCPAIRS * 4];
__device__ __align__(16) ull g_refPair[REFPAIRS * 4];
__device__ float2   g_pcXY[NPC_PAD];
__device__ float2   g_refXY[NREF_PAD];
__device__ unsigned g_min1[NPC_PAD];    // key-min of (|r|^2 - 2 p.r) per pc
__device__ unsigned g_min2[NREF_PAD];   // key-min of (|p|^2 - 2 p.r) per ref
__device__ unsigned g_done;

// ---------------- packed f32x2 helpers ----------------
static __device__ __forceinline__ ull pk2(float lo, float hi) {
    ull r; asm("mov.b64 %0, {%1, %2};" : "=l"(r) : "f"(lo), "f"(hi)); return r;
}
static __device__ __forceinline__ ull vfma2(ull a, ull b, ull c) {
    ull r; asm("fma.rn.f32x2 %0, %1, %2, %3;" : "=l"(r) : "l"(a), "l"(b), "l"(c)); return r;
}
// free register-half selection (no asm boundary -> ptxas renames, no MOVs)
static __device__ __forceinline__ float lo32(ull v) { return __uint_as_float((unsigned)v); }
static __device__ __forceinline__ float hi32(ull v) { return __uint_as_float((unsigned)(v >> 32)); }

// monotone float <-> uint key (handles negatives) for atomicMin
static __device__ __forceinline__ unsigned enc(float f) {
    unsigned u = __float_as_uint(f);
    return u ^ (((unsigned)((int)u >> 31)) | 0x80000000u);
}
static __device__ __forceinline__ float dec(unsigned k) {
    unsigned b = (k & 0x80000000u) ? (k ^ 0x80000000u) : ~k;
    return __uint_as_float(b);
}

// ---------------------------------------------------------------------------
// K1: gather subsampled points (fp32 linspace trunc semantics), build packed
//     pair arrays + scalar arrays, init min arrays + done counter.
//     Pad slots: x=y=0, s=1e30 -> never win a sweep min; pad min entries are
//     written but skipped by the reduce.
// ---------------------------------------------------------------------------
__global__ void k_init(const float* __restrict__ in0, const float* __restrict__ in1) {
    int i = blockIdx.x * 256 + threadIdx.x;   // pair index
    const float D1 = 63999.0f / 7999.0f;      // fp32 rn, compile time
    const float D2 = 79999.0f / 9999.0f;

    if (i < PCPAIRS) {
        float x[2], y[2], s[2];
#pragma unroll
        for (int k = 0; k < 2; k++) {
            int p = 2 * i + k;
            if (p < NPC) {
                int sp = (int)((float)p * D1);
                x[k] = in0[2 * sp]; y[k] = in0[2 * sp + 1];
                s[k] = x[k] * x[k] + y[k] * y[k];
            } else { x[k] = 0.0f; y[k] = 0.0f; s[k] = PAD_S; }
            g_pcXY[p] = make_float2(x[k], y[k]);
            g_min1[p] = 0xFFFFFFFFu;
        }
        g_pcPair[4 * i + 0] = pk2(x[0], x[1]);
        g_pcPair[4 * i + 1] = pk2(y[0], y[1]);
        g_pcPair[4 * i + 2] = pk2(s[0], s[1]);
        g_pcPair[4 * i + 3] = 0ull;
    }
    if (i < REFPAIRS) {
        float x[2], y[2], s[2];
#pragma unroll
        for (int k = 0; k < 2; k++) {
            int p = 2 * i + k;
            if (p < NREF) {
                int sp = (int)((float)p * D2);
                x[k] = in1[2 * sp]; y[k] = in1[2 * sp + 1];
                s[k] = x[k] * x[k] + y[k] * y[k];
            } else { x[k] = 0.0f; y[k] = 0.0f; s[k] = PAD_S; }
            g_refXY[p] = make_float2(x[k], y[k]);
            g_min2[p] = 0xFFFFFFFFu;
        }
        g_refPair[4 * i + 0] = pk2(x[0], x[1]);
        g_refPair[4 * i + 1] = pk2(y[0], y[1]);
        g_refPair[4 * i + 2] = pk2(s[0], s[1]);
        g_refPair[4 * i + 3] = 0ull;
    }
    if (i == 0) g_done = 0u;
}

// ---------------------------------------------------------------------------
// K2: main. Block (cx,cy): pc tile [cy*256,+256) x ref tile [cx*256,+256).
//  Both tiles loaded to shared, ONE sync, then a single interleaved loop:
//   A-side: owned pc (pcBase+t, +128+t) vs swept ref pair j  -> min1 terms
//   B-side: owned ref (refBase+t, +128+t) vs swept pc pair j -> min2 terms
//  4 independent FFMA2 chains per iter; min merges shaped for FMNMX3 fusion.
//  Last block (ticket) reduces: d = sqrt(max(min + |own|^2, 0)), means, out.
// ---------------------------------------------------------------------------
__global__ void __launch_bounds__(NT) k_main(float* __restrict__ out) {
    __shared__ __align__(16) ull shR[TILP * 4];   // 4KB ref tile
    __shared__ __align__(16) ull shP[TILP * 4];   // 4KB pc tile
    __shared__ float sred[8];
    __shared__ int   sflag;

    int b = blockIdx.x, t = threadIdx.x;
    int cx = b % GRID_REF, cy = b / GRID_REF;
    int refBase = cx * TIL;     // point index
    int pcBase  = cy * TIL;

    // ---- load both swept tiles ----
    {
        const ulonglong2* srcR = (const ulonglong2*)(g_refPair + (size_t)(cx * TILP) * 4);
        const ulonglong2* srcP = (const ulonglong2*)(g_pcPair  + (size_t)(cy * TILP) * 4);
        ulonglong2* dstR = (ulonglong2*)shR;
        ulonglong2* dstP = (ulonglong2*)shP;
#pragma unroll
        for (int k = t; k < TILP * 2; k += NT) { dstR[k] = srcR[k]; dstP[k] = srcP[k]; }
    }

    // owned-point broadcast packs (hoisted; overlap with tile load)
    float2 p0 = g_pcXY[pcBase + t];
    float2 p1 = g_pcXY[pcBase + NT + t];
    float2 r0 = g_refXY[refBase + t];
    float2 r1 = g_refXY[refBase + NT + t];
    ull pX0 = pk2(-2.0f * p0.x, -2.0f * p0.x);
    ull pY0 = pk2(-2.0f * p0.y, -2.0f * p0.y);
    ull pX1 = pk2(-2.0f * p1.x, -2.0f * p1.x);
    ull pY1 = pk2(-2.0f * p1.y, -2.0f * p1.y);
    ull rX0 = pk2(-2.0f * r0.x, -2.0f * r0.x);
    ull rY0 = pk2(-2.0f * r0.y, -2.0f * r0.y);
    ull rX1 = pk2(-2.0f * r1.x, -2.0f * r1.x);
    ull rY1 = pk2(-2.0f * r1.y, -2.0f * r1.y);

    __syncthreads();

    float mA0 = PAD_S, mA1 = PAD_S, mB0 = PAD_S, mB1 = PAD_S;

#pragma unroll 4
    for (int j = 0; j < TILP; j++) {
        ulonglong2 vr = *((const ulonglong2*)&shR[4 * j]);   // ref {x0,x1},{y0,y1}
        ull Sr = shR[4 * j + 2];                             // ref {s0,s1}
        ulonglong2 vp = *((const ulonglong2*)&shP[4 * j]);   // pc  packs
        ull Sp = shP[4 * j + 2];

        ull a0 = vfma2(pX0, vr.x, vfma2(pY0, vr.y, Sr));
        ull a1 = vfma2(pX1, vr.x, vfma2(pY1, vr.y, Sr));
        ull b0 = vfma2(rX0, vp.x, vfma2(rY0, vp.y, Sp));
        ull b1 = vfma2(rX1, vp.x, vfma2(rY1, vp.y, Sp));

        mA0 = fminf(fminf(mA0, lo32(a0)), hi32(a0));   // FMNMX3-shaped
        mA1 = fminf(fminf(mA1, lo32(a1)), hi32(a1));
        mB0 = fminf(fminf(mB0, lo32(b0)), hi32(b0));
        mB1 = fminf(fminf(mB1, lo32(b1)), hi32(b1));
    }

    atomicMin(&g_min1[pcBase + t],       enc(mA0));
    atomicMin(&g_min1[pcBase + NT + t],  enc(mA1));
    atomicMin(&g_min2[refBase + t],      enc(mB0));
    atomicMin(&g_min2[refBase + NT + t], enc(mB1));

    // ---- last-block tail reduction ----
    __threadfence();
    __syncthreads();
    if (t == 0) sflag = (atomicAdd(&g_done, 1u) == (unsigned)(NBLOCKS - 1));
    __syncthreads();
    if (!sflag) return;
    __threadfence();

    float s1 = 0.0f, s2 = 0.0f;
    for (int i = t; i < NPC; i += NT) {
        float2 p = g_pcXY[i];
        float v = dec(__ldcg(&g_min1[i])) + (p.x * p.x + p.y * p.y);
        s1 += sqrtf(fmaxf(v, 0.0f));
    }
    for (int j = t; j < NREF; j += NT) {
        float2 r = g_refXY[j];
        float v = dec(__ldcg(&g_min2[j])) + (r.x * r.x + r.y * r.y);
        s2 += sqrtf(fmaxf(v, 0.0f));
    }
#pragma unroll
    for (int off = 16; off > 0; off >>= 1) {
        s1 += __shfl_down_sync(0xFFFFFFFFu, s1, off);
        s2 += __shfl_down_sync(0xFFFFFFFFu, s2, off);
    }
    int w = t >> 5;
    if ((t & 31) == 0) { sred[2 * w] = s1; sred[2 * w + 1] = s2; }
    __syncthreads();
    if (t == 0) {
        float S1 = sred[0] + sred[2] + sred[4] + sred[6];
        float S2 = sred[1] + sred[3] + sred[5] + sred[7];
        out[0] = (S1 * (1.0f / NPC) + S2 * (1.0f / NREF)) * 0.5f;
    }
}

extern "C" void kernel_launch(void* const* d_in, const int* in_sizes, int n_in,
                              void* d_out, int out_size) {
    const float* in0 = (const float*)d_in[0];   // img_render_points
    const float* in1 = (const float*)d_in[1];   // ref point cloud
    float* out = (float*)d_out;

    k_init<<<20, 256>>>(in0, in1);
    k_main<<<NBLOCKS, NT>>>(out);
}

// round 8
// speedup vs baseline: 1.4089x; 1.4089x over previous
#include <cuda_runtime.h>
#include <cstdint>

// ---------------- problem constants ----------------
#define NPC       8000          // 64000/8 render points
#define NPC_PAD   8192
#define NREF      10000         // 80000/8 ref points
#define NREF_PAD  10240
#define PCPAIRS   (NPC_PAD / 2)    // 4096
#define REFPAIRS  (NREF_PAD / 2)   // 5120
#define TOWN      512           // owned points per block (4 per thread)
#define TSWP      512           // swept points per block
#define TSWPP     (TSWP / 2)    // 256 packed swept pairs
#define GRID_A    ((NPC_PAD / TOWN) * (NREF_PAD / TSWP))   // 16*20 = 320
#define GRID_B    ((NREF_PAD / TOWN) * (NPC_PAD / TSWP))   // 20*16 = 320
#define NBLOCKS   (GRID_A + GRID_B)                        // 640
#define NT        128
#define PAD_S     1e30f

typedef unsigned long long ull;

// ---------------- device scratch (no cudaMalloc allowed) ----------------
// Split packed-pair arrays: {x0,x1},{y0,y1} as ulonglong2, {s0,s1} separate.
__device__ __align__(16) ulonglong2 g_pcXXYY[PCPAIRS];
__device__ ull                      g_pcSS[PCPAIRS];
__device__ __align__(16) ulonglong2 g_refXXYY[REFPAIRS];
__device__ ull                      g_refSS[REFPAIRS];
__device__ float2   g_pcXY[NPC_PAD];
__device__ float2   g_refXY[NREF_PAD];
__device__ unsigned g_min1[NPC_PAD];    // key-min of (|r|^2 - 2 p.r) per pc
__device__ unsigned g_min2[NREF_PAD];   // key-min of (|p|^2 - 2 p.r) per ref
__device__ unsigned g_done;

// ---------------- packed f32x2 helpers ----------------
static __device__ __forceinline__ ull pk2(float lo, float hi) {
    ull r; asm("mov.b64 %0, {%1, %2};" : "=l"(r) : "f"(lo), "f"(hi)); return r;
}
// q = fma2(X, vx, fma2(Y, vy, S)); split halves via mov.b64 (rename, no SHF)
static __device__ __forceinline__ void dist2(ull X, ull Y, ull vx, ull vy, ull S,
                                             float& lo, float& hi) {
    ull q;
    asm("fma.rn.f32x2 %0, %1, %2, %3;" : "=l"(q) : "l"(Y), "l"(vy), "l"(S));
    asm("fma.rn.f32x2 %0, %1, %2, %3;" : "=l"(q) : "l"(X), "l"(vx), "l"(q));
    asm("mov.b64 {%0, %1}, %2;" : "=f"(lo), "=f"(hi) : "l"(q));
}

// monotone float <-> uint key (handles negatives) for atomicMin
static __device__ __forceinline__ unsigned enc(float f) {
    unsigned u = __float_as_uint(f);
    return u ^ (((unsigned)((int)u >> 31)) | 0x80000000u);
}
static __device__ __forceinline__ float dec(unsigned k) {
    unsigned b = (k & 0x80000000u) ? (k ^ 0x80000000u) : ~k;
    return __uint_as_float(b);
}

// ---------------------------------------------------------------------------
// K1: gather subsampled points (fp32 linspace trunc semantics), build packed
//     pair arrays + float2 arrays, init min arrays + done counter.
//     Pad slots: x=y=0, s=1e30 -> never win a sweep; pad min entries written
//     but skipped by the reduce.
// ---------------------------------------------------------------------------
__global__ void k_init(const float* __restrict__ in0, const float* __restrict__ in1) {
    int i = blockIdx.x * 256 + threadIdx.x;   // pair index
    const float D1 = 63999.0f / 7999.0f;      // fp32 rn, compile time
    const float D2 = 79999.0f / 9999.0f;

    if (i < PCPAIRS) {
        float x[2], y[2], s[2];
#pragma unroll
        for (int k = 0; k < 2; k++) {
            int p = 2 * i + k;
            if (p < NPC) {
                int sp = (int)((float)p * D1);
                x[k] = in0[2 * sp]; y[k] = in0[2 * sp + 1];
                s[k] = x[k] * x[k] + y[k] * y[k];
            } else { x[k] = 0.0f; y[k] = 0.0f; s[k] = PAD_S; }
            g_pcXY[p] = make_float2(x[k], y[k]);
            g_min1[p] = 0xFFFFFFFFu;
        }
        ulonglong2 v; v.x = pk2(x[0], x[1]); v.y = pk2(y[0], y[1]);
        g_pcXXYY[i] = v;
        g_pcSS[i]   = pk2(s[0], s[1]);
    }
    if (i < REFPAIRS) {
        float x[2], y[2], s[2];
#pragma unroll
        for (int k = 0; k < 2; k++) {
            int p = 2 * i + k;
            if (p < NREF) {
                int sp = (int)((float)p * D2);
                x[k] = in1[2 * sp]; y[k] = in1[2 * sp + 1];
                s[k] = x[k] * x[k] + y[k] * y[k];
            } else { x[k] = 0.0f; y[k] = 0.0f; s[k] = PAD_S; }
            g_refXY[p] = make_float2(x[k], y[k]);
            g_min2[p] = 0xFFFFFFFFu;
        }
        ulonglong2 v; v.x = pk2(x[0], x[1]); v.y = pk2(y[0], y[1]);
        g_refXXYY[i] = v;
        g_refSS[i]   = pk2(s[0], s[1]);
    }
    if (i == 0) g_done = 0u;
}

// ---------------------------------------------------------------------------
// K2: main. 640 blocks, ONE direction each:
//   b <  320 (A): own pc tile [cy*512,+512), sweep ref tile [cx*512,+512)
//   b >= 320 (B): own ref tile, sweep pc tile (roles swapped)
//  Thread owns 4 points (stride-128) as {-2x,-2x}/{-2y,-2y} broadcast packs
//  (8 ull = 16 regs), sweeps 256 packed pairs from shared:
//    per iter: LDS.128 + LDS.64 + 8 FFMA2 + 4 min merges  (8 pairs).
//  Last block (ticket) reduces: d = sqrt(max(min + |own|^2, 0)), means, out.
// ---------------------------------------------------------------------------
__global__ void __launch_bounds__(NT) k_main(float* __restrict__ out) {
    __shared__ __align__(16) ulonglong2 shXY[TSWPP];   // 4KB
    __shared__ ull                      shS[TSWPP];    // 2KB
    __shared__ float sred[8];
    __shared__ int   sflag;

    int b = blockIdx.x, t = threadIdx.x;

    const ulonglong2* sweptXY;
    const ull*        sweptS;
    const float2*     ownXY;
    unsigned*         minArr;
    int ownBase, swpBase;

    if (b < GRID_A) {                 // A: own pc, sweep ref
        int cy = b & 15;              // pc tile 0..15
        int cx = b >> 4;              // ref tile 0..19
        ownBase = cy * TOWN;
        swpBase = cx * TSWPP;
        sweptXY = g_refXXYY; sweptS = g_refSS;
        ownXY   = g_pcXY;    minArr = g_min1;
    } else {                          // B: own ref, sweep pc
        int bb = b - GRID_A;
        int cy = bb % 20;             // ref tile 0..19
        int cx = bb / 20;             // pc tile 0..15
        ownBase = cy * TOWN;
        swpBase = cx * TSWPP;
        sweptXY = g_pcXXYY;  sweptS = g_pcSS;
        ownXY   = g_refXY;   minArr = g_min2;
    }

    // ---- load swept tile ----
#pragma unroll
    for (int k = t; k < TSWPP; k += NT) {
        shXY[k] = sweptXY[swpBase + k];
        shS[k]  = sweptS[swpBase + k];
    }

    // ---- owned broadcast packs (overlap with tile load) ----
    float2 o0 = ownXY[ownBase + t];
    float2 o1 = ownXY[ownBase + NT + t];
    float2 o2 = ownXY[ownBase + 2 * NT + t];
    float2 o3 = ownXY[ownBase + 3 * NT + t];
    ull X0 = pk2(-2.0f * o0.x, -2.0f * o0.x), Y0 = pk2(-2.0f * o0.y, -2.0f * o0.y);
    ull X1 = pk2(-2.0f * o1.x, -2.0f * o1.x), Y1 = pk2(-2.0f * o1.y, -2.0f * o1.y);
    ull X2 = pk2(-2.0f * o2.x, -2.0f * o2.x), Y2 = pk2(-2.0f * o2.y, -2.0f * o2.y);
    ull X3 = pk2(-2.0f * o3.x, -2.0f * o3.x), Y3 = pk2(-2.0f * o3.y, -2.0f * o3.y);

    __syncthreads();

    float m0 = PAD_S, m1 = PAD_S, m2 = PAD_S, m3 = PAD_S;

#pragma unroll 8
    for (int j = 0; j < TSWPP; j++) {
        ulonglong2 v = shXY[j];
        ull        S = shS[j];
        float l0, h0, l1, h1, l2, h2, l3, h3;
        dist2(X0, Y0, v.x, v.y, S, l0, h0);
        dist2(X1, Y1, v.x, v.y, S, l1, h1);
        dist2(X2, Y2, v.x, v.y, S, l2, h2);
        dist2(X3, Y3, v.x, v.y, S, l3, h3);
        m0 = fminf(m0, fminf(l0, h0));   // FMNMX3-shaped
        m1 = fminf(m1, fminf(l1, h1));
        m2 = fminf(m2, fminf(l2, h2));
        m3 = fminf(m3, fminf(l3, h3));
    }

    atomicMin(&minArr[ownBase + t],          enc(m0));
    atomicMin(&minArr[ownBase + NT + t],     enc(m1));
    atomicMin(&minArr[ownBase + 2 * NT + t], enc(m2));
    atomicMin(&minArr[ownBase + 3 * NT + t], enc(m3));

    // ---- last-block tail reduction ----
    __threadfence();
    __syncthreads();
    if (t == 0) sflag = (atomicAdd(&g_done, 1u) == (unsigned)(NBLOCKS - 1));
    __syncthreads();
    if (!sflag) return;
    __threadfence();

    float s1 = 0.0f, s2 = 0.0f;
    for (int i = t; i < NPC; i += NT) {
        float2 p = g_pcXY[i];
        float v = dec(__ldcg(&g_min1[i])) + (p.x * p.x + p.y * p.y);
        s1 += sqrtf(fmaxf(v, 0.0f));
    }
    for (int j = t; j < NREF; j += NT) {
        float2 r = g_refXY[j];
        float v = dec(__ldcg(&g_min2[j])) + (r.x * r.x + r.y * r.y);
        s2 += sqrtf(fmaxf(v, 0.0f));
    }
#pragma unroll
    for (int off = 16; off > 0; off >>= 1) {
        s1 += __shfl_down_sync(0xFFFFFFFFu, s1, off);
        s2 += __shfl_down_sync(0xFFFFFFFFu, s2, off);
    }
    int w = t >> 5;
    if ((t & 31) == 0) { sred[2 * w] = s1; sred[2 * w + 1] = s2; }
    __syncthreads();
    if (t == 0) {
        float S1 = sred[0] + sred[2] + sred[4] + sred[6];
        float S2 = sred[1] + sred[3] + sred[5] + sred[7];
        out[0] = (S1 * (1.0f / NPC) + S2 * (1.0f / NREF)) * 0.5f;
    }
}

extern "C" void kernel_launch(void* const* d_in, const int* in_sizes, int n_in,
                              void* d_out, int out_size) {
    const float* in0 = (const float*)d_in[0];   // img_render_points
    const float* in1 = (const float*)d_in[1];   // ref point cloud
    float* out = (float*)d_out;

    k_init<<<20, 256>>>(in0, in1);
    k_main<<<NBLOCKS, NT>>>(out);
}

// round 9
// speedup vs baseline: 1.4203x; 1.0080x over previous
#include <cuda_runtime.h>
#include <cstdint>

// ---------------- problem constants ----------------
#define NPC       8000          // 64000/8 render points
#define NPC_PAD   8192
#define NREF      10000         // 80000/8 ref points
#define NREF_PAD  10240
#define PCPAIRS   (NPC_PAD / 2)    // 4096
#define REFPAIRS  (NREF_PAD / 2)   // 5120
#define TOWN      512           // owned points per block (4 per thread)
#define TSWP      256           // swept points per block
#define TSWPP     (TSWP / 2)    // 128 packed swept pairs
#define GRID_A    ((NPC_PAD / TOWN) * (NREF_PAD / TSWP))   // 16*40 = 640
#define GRID_B    ((NREF_PAD / TOWN) * (NPC_PAD / TSWP))   // 20*32 = 640
#define NBLOCKS   (GRID_A + GRID_B)                        // 1280
#define NT        128
#define PAD_S     1e30f

typedef unsigned long long ull;

// ---------------- device scratch (no cudaMalloc allowed) ----------------
// Split packed-pair arrays: {x0,x1},{y0,y1} as ulonglong2, {s0,s1} separate.
__device__ __align__(16) ulonglong2 g_pcXXYY[PCPAIRS];
__device__ ull                      g_pcSS[PCPAIRS];
__device__ __align__(16) ulonglong2 g_refXXYY[REFPAIRS];
__device__ ull                      g_refSS[REFPAIRS];
__device__ float2   g_pcXY[NPC_PAD];
__device__ float2   g_refXY[NREF_PAD];
__device__ unsigned g_min1[NPC_PAD];    // key-min of (|r|^2 - 2 p.r) per pc
__device__ unsigned g_min2[NREF_PAD];   // key-min of (|p|^2 - 2 p.r) per ref
__device__ unsigned g_done;

// ---------------- packed f32x2 helpers ----------------
static __device__ __forceinline__ ull pk2(float lo, float hi) {
    ull r; asm("mov.b64 %0, {%1, %2};" : "=l"(r) : "f"(lo), "f"(hi)); return r;
}
// q = fma2(X, vx, fma2(Y, vy, S)); split halves via mov.b64 (rename, no SHF)
static __device__ __forceinline__ void dist2(ull X, ull Y, ull vx, ull vy, ull S,
                                             float& lo, float& hi) {
    ull q;
    asm("fma.rn.f32x2 %0, %1, %2, %3;" : "=l"(q) : "l"(Y), "l"(vy), "l"(S));
    asm("fma.rn.f32x2 %0, %1, %2, %3;" : "=l"(q) : "l"(X), "l"(vx), "l"(q));
    asm("mov.b64 {%0, %1}, %2;" : "=f"(lo), "=f"(hi) : "l"(q));
}

// monotone float <-> uint key (handles negatives) for atomicMin
static __device__ __forceinline__ unsigned enc(float f) {
    unsigned u = __float_as_uint(f);
    return u ^ (((unsigned)((int)u >> 31)) | 0x80000000u);
}
static __device__ __forceinline__ float dec(unsigned k) {
    unsigned b = (k & 0x80000000u) ? (k ^ 0x80000000u) : ~k;
    return __uint_as_float(b);
}

// ---------------------------------------------------------------------------
// K1: gather subsampled points (fp32 linspace trunc semantics), build packed
//     pair arrays + float2 arrays, init min arrays + done counter.
//     Pad slots: x=y=0, s=1e30 -> never win a sweep; pad min entries written
//     but skipped by the reduce.
// ---------------------------------------------------------------------------
__global__ void k_init(const float* __restrict__ in0, const float* __restrict__ in1) {
    int i = blockIdx.x * 256 + threadIdx.x;   // pair index
    const float D1 = 63999.0f / 7999.0f;      // fp32 rn, compile time
    const float D2 = 79999.0f / 9999.0f;

    if (i < PCPAIRS) {
        float x[2], y[2], s[2];
#pragma unroll
        for (int k = 0; k < 2; k++) {
            int p = 2 * i + k;
            if (p < NPC) {
                int sp = (int)((float)p * D1);
                x[k] = in0[2 * sp]; y[k] = in0[2 * sp + 1];
                s[k] = x[k] * x[k] + y[k] * y[k];
            } else { x[k] = 0.0f; y[k] = 0.0f; s[k] = PAD_S; }
            g_pcXY[p] = make_float2(x[k], y[k]);
            g_min1[p] = 0xFFFFFFFFu;
        }
        ulonglong2 v; v.x = pk2(x[0], x[1]); v.y = pk2(y[0], y[1]);
        g_pcXXYY[i] = v;
        g_pcSS[i]   = pk2(s[0], s[1]);
    }
    if (i < REFPAIRS) {
        float x[2], y[2], s[2];
#pragma unroll
        for (int k = 0; k < 2; k++) {
            int p = 2 * i + k;
            if (p < NREF) {
                int sp = (int)((float)p * D2);
                x[k] = in1[2 * sp]; y[k] = in1[2 * sp + 1];
                s[k] = x[k] * x[k] + y[k] * y[k];
            } else { x[k] = 0.0f; y[k] = 0.0f; s[k] = PAD_S; }
            g_refXY[p] = make_float2(x[k], y[k]);
            g_min2[p] = 0xFFFFFFFFu;
        }
        ulonglong2 v; v.x = pk2(x[0], x[1]); v.y = pk2(y[0], y[1]);
        g_refXXYY[i] = v;
        g_refSS[i]   = pk2(s[0], s[1]);
    }
    if (i == 0) g_done = 0u;
}

// ---------------------------------------------------------------------------
// K2: main. 1280 blocks, ONE direction each:
//   b <  640 (A): own pc tile [cy*512,+512), sweep ref chunk [cx*256,+256)
//   b >= 640 (B): own ref tile [cy*512,+512), sweep pc chunk [cx*256,+256)
//  Thread owns 4 points (stride-128) as {-2x,-2x}/{-2y,-2y} broadcast packs
//  (8 ull = 16 regs), sweeps 128 packed pairs from shared:
//    per iter: LDS.128 + LDS.64 + 8 FFMA2 + 8 FMNMX  (8 pairs).
//  launch_bounds(128,6) -> reg cap 85: lets ptxas batch LDS across the
//  unroll-8 window and hide the 29-cyc shared latency.
//  Last block (ticket) reduces: d = sqrt(max(min + |own|^2, 0)), means, out.
// ---------------------------------------------------------------------------
__global__ void __launch_bounds__(NT, 6) k_main(float* __restrict__ out) {
    __shared__ __align__(16) ulonglong2 shXY[TSWPP];   // 2KB
    __shared__ ull                      shS[TSWPP];    // 1KB
    __shared__ float sred[8];
    __shared__ int   sflag;

    int b = blockIdx.x, t = threadIdx.x;

    const ulonglong2* sweptXY;
    const ull*        sweptS;
    const float2*     ownXY;
    unsigned*         minArr;
    int ownBase, swpBase;

    if (b < GRID_A) {                 // A: own pc, sweep ref
        int cy = b & 15;              // pc tile 0..15
        int cx = b >> 4;              // ref chunk 0..39
        ownBase = cy * TOWN;
        swpBase = cx * TSWPP;
        sweptXY = g_refXXYY; sweptS = g_refSS;
        ownXY   = g_pcXY;    minArr = g_min1;
    } else {                          // B: own ref, sweep pc
        int bb = b - GRID_A;
        int cy = bb % 20;             // ref tile 0..19
        int cx = bb / 20;             // pc chunk 0..31
        ownBase = cy * TOWN;
        swpBase = cx * TSWPP;
        sweptXY = g_pcXXYY;  sweptS = g_pcSS;
        ownXY   = g_refXY;   minArr = g_min2;
    }

    // ---- load swept tile (128 pairs) ----
    if (t < TSWPP) {
        shXY[t] = sweptXY[swpBase + t];
        shS[t]  = sweptS[swpBase + t];
    }

    // ---- owned broadcast packs (overlap with tile load) ----
    float2 o0 = ownXY[ownBase + t];
    float2 o1 = ownXY[ownBase + NT + t];
    float2 o2 = ownXY[ownBase + 2 * NT + t];
    float2 o3 = ownXY[ownBase + 3 * NT + t];
    ull X0 = pk2(-2.0f * o0.x, -2.0f * o0.x), Y0 = pk2(-2.0f * o0.y, -2.0f * o0.y);
    ull X1 = pk2(-2.0f * o1.x, -2.0f * o1.x), Y1 = pk2(-2.0f * o1.y, -2.0f * o1.y);
    ull X2 = pk2(-2.0f * o2.x, -2.0f * o2.x), Y2 = pk2(-2.0f * o2.y, -2.0f * o2.y);
    ull X3 = pk2(-2.0f * o3.x, -2.0f * o3.x), Y3 = pk2(-2.0f * o3.y, -2.0f * o3.y);

    __syncthreads();

    float m0 = PAD_S, m1 = PAD_S, m2 = PAD_S, m3 = PAD_S;

#pragma unroll 8
    for (int j = 0; j < TSWPP; j++) {
        ulonglong2 v = shXY[j];
        ull        S = shS[j];
        float l0, h0, l1, h1, l2, h2, l3, h3;
        dist2(X0, Y0, v.x, v.y, S, l0, h0);
        dist2(X1, Y1, v.x, v.y, S, l1, h1);
        dist2(X2, Y2, v.x, v.y, S, l2, h2);
        dist2(X3, Y3, v.x, v.y, S, l3, h3);
        m0 = fminf(m0, fminf(l0, h0));   // FMNMX3-shaped
        m1 = fminf(m1, fminf(l1, h1));
        m2 = fminf(m2, fminf(l2, h2));
        m3 = fminf(m3, fminf(l3, h3));
    }

    atomicMin(&minArr[ownBase + t],          enc(m0));
    atomicMin(&minArr[ownBase + NT + t],     enc(m1));
    atomicMin(&minArr[ownBase + 2 * NT + t], enc(m2));
    atomicMin(&minArr[ownBase + 3 * NT + t], enc(m3));

    // ---- last-block tail reduction ----
    __threadfence();
    __syncthreads();
    if (t == 0) sflag = (atomicAdd(&g_done, 1u) == (unsigned)(NBLOCKS - 1));
    __syncthreads();
    if (!sflag) return;
    __threadfence();

    float s1 = 0.0f, s2 = 0.0f;
    for (int i = t; i < NPC; i += NT) {
        float2 p = g_pcXY[i];
        float v = dec(__ldcg(&g_min1[i])) + (p.x * p.x + p.y * p.y);
        s1 += sqrtf(fmaxf(v, 0.0f));
    }
    for (int j = t; j < NREF; j += NT) {
        float2 r = g_refXY[j];
        float v = dec(__ldcg(&g_min2[j])) + (r.x * r.x + r.y * r.y);
        s2 += sqrtf(fmaxf(v, 0.0f));
    }
#pragma unroll
    for (int off = 16; off > 0; off >>= 1) {
        s1 += __shfl_down_sync(0xFFFFFFFFu, s1, off);
        s2 += __shfl_down_sync(0xFFFFFFFFu, s2, off);
    }
    int w = t >> 5;
    if ((t & 31) == 0) { sred[2 * w] = s1; sred[2 * w + 1] = s2; }
    __syncthreads();
    if (t == 0) {
        float S1 = sred[0] + sred[2] + sred[4] + sred[6];
        float S2 = sred[1] + sred[3] + sred[5] + sred[7];
        out[0] = (S1 * (1.0f / NPC) + S2 * (1.0f / NREF)) * 0.5f;
    }
}

extern "C" void kernel_launch(void* const* d_in, const int* in_sizes, int n_in,
                              void* d_out, int out_size) {
    const float* in0 = (const float*)d_in[0];   // img_render_points
    const float* in1 = (const float*)d_in[1];   // ref point cloud
    float* out = (float*)d_out;

    k_init<<<20, 256>>>(in0, in1);
    k_main<<<NBLOCKS, NT>>>(out);
}